// round 5
// baseline (speedup 1.0000x reference)
#include <cuda_runtime.h>
#include <cuda_fp16.h>
#include <math.h>

#define NODECAP 16384
#define G_TOTAL 237568   // 192*384 + 256*512 + 128*256
#define PRECAP  (1<<20)
#define SMEM_BYTES 131072   // 2 mats * 128 edges * 256 cols * 2B

// Prepped fragment-major fp16 weights: [0]=q_hi [1]=q_lo [2]=k_hi [3]=k_lo
__device__ __align__(16) __half g_B[4][G_TOTAL];
__device__ float    g_pre[PRECAP];
__device__ unsigned g_segmax[NODECAP * 8];
__device__ float    g_segsum[NODECAP * 8];

__constant__ int c_ord[9] = {0, 2, 6, 3, 7, 1, 5, 8, 4};
__constant__ int c_KT[3]  = {12, 16, 8};
__constant__ int c_NP[3]  = {24, 32, 16};
__constant__ int c_NPJ[3] = {6, 8, 4};
__constant__ int c_D[3]   = {192, 256, 128};
__constant__ int c_IB0[3] = {0, 3, 7};
__constant__ int c_B4[3]  = {0, 9216, 25600};   // uint4 base per group

// ---------------------------------------------------------------------------
// Weight prep: dense W_eff per |m| group (sign pattern folded), split fp16
// hi/lo, exact mma.m16n8k16 B-fragment order, n8 pairs packed 8 halfs/lane.
// ---------------------------------------------------------------------------
__global__ void prep_w(const float* __restrict__ W, int mat) {
    int idx = blockIdx.x * blockDim.x + threadIdx.x;
    if (idx >= G_TOTAL) return;
    int g, kk, n, NP, boff, rem = idx;
    if (rem < 73728)       { g = 0; kk = rem / 384; n = rem % 384; NP = 24; boff = 0; }
    else if (rem < 204800) { rem -= 73728;  g = 1; kk = rem / 512; n = rem % 512; NP = 32; boff = 73728; }
    else                   { rem -= 204800; g = 2; kk = rem / 256; n = rem % 256; NP = 16; boff = 204800; }

    int c = kk & 63, d = n & 127, ib = kk >> 6, ob = n >> 7;
    int w; float s = 1.0f;
    if (g == 0) {
        w = ib * 3 + ob;
    } else if (g == 1) {
        int i = ib & 1, o = ob & 1;
        bool ip = ib < 2, op = ob < 2;
        int base = 9 + i * 4 + o * 2;
        if (ip && op)        w = base;                   // +Wr
        else if (!ip && op)  { w = base + 1; s = -1.f; } // -Wi
        else if (ip && !op)  w = base + 1;               // +Wi
        else                 w = base;                   // +Wr
    } else {
        bool ip = (ib == 0), op = (ob == 0);
        if (ip && op)        w = 17;
        else if (!ip && op)  { w = 18; s = -1.f; }
        else if (ip && !op)  w = 18;
        else                 w = 17;
    }
    int widx = (w * 64 + c) * 128 + d;

    int kt = kk >> 4, k16 = kk & 15, n8 = n >> 3;
    int lane = (n & 7) * 4 + ((k16 & 7) >> 1);
    int slot = (k16 & 1) + ((k16 >> 3) << 1);
    int off  = boff + ((kt * NP + (n8 >> 1)) * 32 + lane) * 8 + ((n8 & 1) << 2) + slot;

    float v = s * W[widx];
    __half h = __float2half_rn(v);
    g_B[2 * mat][off]     = h;
    g_B[2 * mat + 1][off] = __float2half_rn(v - __half2float(h));
}

// ---------------------------------------------------------------------------
#define MMA(c, a, b0, b1) asm volatile( \
    "mma.sync.aligned.m16n8k16.row.col.f32.f16.f16.f32 " \
    "{%0,%1,%2,%3},{%4,%5,%6,%7},{%8,%9},{%0,%1,%2,%3};\n" \
    : "+f"((c)[0]), "+f"((c)[1]), "+f"((c)[2]), "+f"((c)[3]) \
    : "r"((a).x), "r"((a).y), "r"((a).z), "r"((a).w), "r"(b0), "r"(b1))

__global__ __launch_bounds__(256, 1)
void so2_attn_main(const float* __restrict__ xq, const float* __restrict__ xk, int E) {
    extern __shared__ __half sA[];   // [0]=q frags (32768 halfs), [32768]=k frags
    const int tid = threadIdx.x, lane = tid & 31, warp = tid >> 5;
    const int warpM = warp & 1, warpN = warp >> 1;
    const int tileE = blockIdx.x * 128;

    float pre[4][2][2];   // [mtl][rowhalf][par] ; head = warpN + par*4
    #pragma unroll
    for (int a = 0; a < 4; a++)
        #pragma unroll
        for (int b = 0; b < 2; b++)
            #pragma unroll
            for (int c = 0; c < 2; c++) pre[a][b][c] = 0.f;

    for (int g = 0; g < 3; ++g) {
        const int Kt = c_KT[g], NP = c_NP[g], NPJ = c_NPJ[g], D = c_D[g];
        __syncthreads();
        // ---- convert x slice -> fragment-major fp16 smem (128 edges) ----
        const int nq = 128 * (D >> 2);
        #pragma unroll
        for (int t = 0; t < 2; ++t) {
            const float* x = t ? xk : xq;
            __half* A = sA + t * 32768;
            for (int q0 = tid; q0 < nq; q0 += 256) {
                int el = q0 / (D >> 2), c = (q0 % (D >> 2)) * 4;
                int ord = c_ord[c_IB0[g] + (c >> 6)];
                int e = tileE + el;
                float4 v = make_float4(0.f, 0.f, 0.f, 0.f);
                if (e < E) v = *(const float4*)(x + ((size_t)e * 9 + ord) * 64 + (c & 63));
                int r = el & 15, mtile = el >> 4;
                int kt = c >> 4, kk0 = c & 15;
                int ln0 = (r & 7) * 4 + ((kk0 & 7) >> 1);
                int hx  = (((kk0 >> 3) << 1) + (r >> 3)) * 2;
                int off = ((mtile * Kt + kt) * 32 + ln0) * 8 + hx;
                *(__half2*)(A + off)     = __floats2half2_rn(v.x, v.y);
                *(__half2*)(A + off + 8) = __floats2half2_rn(v.z, v.w);
            }
        }
        __syncthreads();

        // ---- fused 2-pass (W hi/lo) fp16 GEMMs + per-head q*k reduction ----
        const uint4* Bqh = (const uint4*)g_B[0] + c_B4[g];
        const uint4* Bql = (const uint4*)g_B[1] + c_B4[g];
        const uint4* Bkh = (const uint4*)g_B[2] + c_B4[g];
        const uint4* Bkl = (const uint4*)g_B[3] + c_B4[g];
        const uint4* Aq = (const uint4*)sA;
        const uint4* Ak = Aq + 4096;
        const int bstep = NP * 32;

        for (int j = 0; j < NPJ; ++j) {
            const int p0 = warpN + (j << 2);
            float cq[4][2][4], ck[4][2][4];
            #pragma unroll
            for (int a = 0; a < 4; a++)
                #pragma unroll
                for (int d2 = 0; d2 < 2; d2++)
                    #pragma unroll
                    for (int i = 0; i < 4; i++) { cq[a][d2][i] = 0.f; ck[a][d2][i] = 0.f; }

            int bi = p0 * 32 + lane;
            uint4 bqh = Bqh[bi], bql = Bql[bi], bkh = Bkh[bi], bkl = Bkl[bi];

            #pragma unroll 1
            for (int kt = 0; kt < Kt; ++kt) {
                uint4 aq[4], ak[4];
                #pragma unroll
                for (int mtl = 0; mtl < 4; ++mtl) {
                    int ai = (((warpM << 2) + mtl) * Kt + kt) * 32 + lane;
                    aq[mtl] = Aq[ai]; ak[mtl] = Ak[ai];
                }
                int nbi = (kt + 1 < Kt) ? bi + bstep : bi;
                uint4 nbqh = Bqh[nbi], nbql = Bql[nbi], nbkh = Bkh[nbi], nbkl = Bkl[nbi];

                #pragma unroll
                for (int mtl = 0; mtl < 4; ++mtl) {
                    MMA(cq[mtl][0], aq[mtl], bqh.x, bqh.y);
                    MMA(cq[mtl][1], aq[mtl], bqh.z, bqh.w);
                    MMA(ck[mtl][0], ak[mtl], bkh.x, bkh.y);
                    MMA(ck[mtl][1], ak[mtl], bkh.z, bkh.w);
                    MMA(cq[mtl][0], aq[mtl], bql.x, bql.y);
                    MMA(cq[mtl][1], aq[mtl], bql.z, bql.w);
                    MMA(ck[mtl][0], ak[mtl], bkl.x, bkl.y);
                    MMA(ck[mtl][1], ak[mtl], bkl.z, bkl.w);
                }
                bqh = nbqh; bql = nbql; bkh = nbkh; bkl = nbkl;
                bi = nbi;
            }

            const int par = j & 1;
            #pragma unroll
            for (int mtl = 0; mtl < 4; ++mtl) {
                pre[mtl][0][par] += cq[mtl][0][0] * ck[mtl][0][0] + cq[mtl][0][1] * ck[mtl][0][1]
                                  + cq[mtl][1][0] * ck[mtl][1][0] + cq[mtl][1][1] * ck[mtl][1][1];
                pre[mtl][1][par] += cq[mtl][0][2] * ck[mtl][0][2] + cq[mtl][0][3] * ck[mtl][0][3]
                                  + cq[mtl][1][2] * ck[mtl][1][2] + cq[mtl][1][3] * ck[mtl][1][3];
            }
        }
    }

    // reduce over the 4-lane n-split group and store pre (unique writer per (e,h))
    #pragma unroll
    for (int a = 0; a < 4; a++)
        #pragma unroll
        for (int b = 0; b < 2; b++)
            #pragma unroll
            for (int c = 0; c < 2; c++) {
                float v = pre[a][b][c];
                v += __shfl_xor_sync(0xffffffffu, v, 1);
                v += __shfl_xor_sync(0xffffffffu, v, 2);
                pre[a][b][c] = v;
            }
    if ((lane & 3) == 0) {
        int gID = lane >> 2;
        #pragma unroll
        for (int mtl = 0; mtl < 4; ++mtl)
            #pragma unroll
            for (int rh = 0; rh < 2; ++rh)
                #pragma unroll
                for (int par = 0; par < 2; ++par) {
                    int e = tileE + ((warpM << 2) + mtl) * 16 + gID + rh * 8;
                    int h = warpN + par * 4;
                    if (e < E) g_pre[e * 8 + h] = 0.25f * pre[mtl][rh][par];
                }
    }
}

// ---------------------------------------------------------------------------
// Segment softmax
// ---------------------------------------------------------------------------
__device__ __forceinline__ unsigned fenc(float f) {
    unsigned b = __float_as_uint(f);
    return (b & 0x80000000u) ? ~b : (b | 0x80000000u);
}
__device__ __forceinline__ float fdec(unsigned u) {
    unsigned b = (u & 0x80000000u) ? (u & 0x7FFFFFFFu) : ~u;
    return __uint_as_float(b);
}

__global__ void k_init_max() {
    int i = blockIdx.x * blockDim.x + threadIdx.x;
    if (i < NODECAP * 8) g_segmax[i] = 0u;
}
__global__ void k_init_sum() {
    int i = blockIdx.x * blockDim.x + threadIdx.x;
    if (i < NODECAP * 8) g_segsum[i] = 0.f;
}
__global__ void k_zero_pre(int n) {
    int i = blockIdx.x * blockDim.x + threadIdx.x;
    if (i < n) g_pre[i] = 0.f;
}
__global__ void k_max(int E, const int* __restrict__ index) {
    int i = blockIdx.x * blockDim.x + threadIdx.x;
    if (i >= E * 8) return;
    int e = i >> 3, h = i & 7;
    atomicMax(&g_segmax[index[e] * 8 + h], fenc(g_pre[i]));
}
__global__ void k_exp(int E, const int* __restrict__ index, float* __restrict__ out) {
    int i = blockIdx.x * blockDim.x + threadIdx.x;
    if (i >= E * 8) return;
    int e = i >> 3, h = i & 7;
    int seg = index[e] * 8 + h;
    float ex = expf(g_pre[i] - fdec(g_segmax[seg]));
    out[i] = ex;
    atomicAdd(&g_segsum[seg], ex);
}
__global__ void k_norm(int E, const int* __restrict__ index, float* __restrict__ out) {
    int i = blockIdx.x * blockDim.x + threadIdx.x;
    if (i >= E * 8) return;
    int e = i >> 3, h = i & 7;
    out[i] = out[i] / (g_segsum[index[e] * 8 + h] + 1e-16f);
}

// ---------------------------------------------------------------------------
extern "C" void kernel_launch(void* const* d_in, const int* in_sizes, int n_in,
                              void* d_out, int out_size) {
    const float* xq    = (const float*)d_in[0];
    const float* xk    = (const float*)d_in[1];
    const float* Wq    = (const float*)d_in[2];
    const float* Wk    = (const float*)d_in[3];
    const int*   index = (const int*)d_in[4];
    float* out = (float*)d_out;
    int E = in_sizes[0] / (9 * 64);

    cudaFuncSetAttribute(so2_attn_main, cudaFuncAttributeMaxDynamicSharedMemorySize, SMEM_BYTES);

    // launches 0..4 (setup) so the main GEMM is launch #5 for ncu -s 5 -c 1
    k_init_max<<<(NODECAP * 8 + 255) / 256, 256>>>();
    k_init_sum<<<(NODECAP * 8 + 255) / 256, 256>>>();
    prep_w<<<(G_TOTAL + 255) / 256, 256>>>(Wq, 0);
    prep_w<<<(G_TOTAL + 255) / 256, 256>>>(Wk, 1);
    k_zero_pre<<<(E * 8 + 255) / 256, 256>>>(E * 8);

    so2_attn_main<<<(E + 127) / 128, 256, SMEM_BYTES>>>(xq, xk, E);

    int nb = (E * 8 + 255) / 256;
    k_max <<<nb, 256>>>(E, index);
    k_exp <<<nb, 256>>>(E, index, out);
    k_norm<<<nb, 256>>>(E, index, out);
}

// round 7
// speedup vs baseline: 1.4221x; 1.4221x over previous
#include <cuda_runtime.h>
#include <cuda_fp16.h>
#include <math.h>

#define NODECAP 16384
#define G_TOTAL 237568   // 192*384 + 256*512 + 128*256
#define PRECAP  (1<<20)
#define SMEM_BYTES 131072   // 2 mats * 128 edges * 256 cols * 2B

// Prepped fragment-major fp16 weights: [0]=q [1]=k
__device__ __align__(16) __half g_B[2][G_TOTAL];
__device__ float    g_pre[PRECAP];
__device__ unsigned g_segmax[NODECAP * 8];
__device__ float    g_segsum[NODECAP * 8];

__constant__ int c_ord[9] = {0, 2, 6, 3, 7, 1, 5, 8, 4};
__constant__ int c_KT[3]  = {12, 16, 8};
__constant__ int c_NP[3]  = {24, 32, 16};
__constant__ int c_NPJ[3] = {6, 8, 4};
__constant__ int c_D[3]   = {192, 256, 128};
__constant__ int c_IB0[3] = {0, 3, 7};
__constant__ int c_B4[3]  = {0, 9216, 25600};   // uint4 base per group

// ---------------------------------------------------------------------------
// Weight prep: dense W_eff per |m| group (sign pattern folded), fp16,
// exact mma.m16n8k16 B-fragment order, n8 pairs packed 8 halfs/lane.
// ---------------------------------------------------------------------------
__global__ void prep_w(const float* __restrict__ W, int mat) {
    int idx = blockIdx.x * blockDim.x + threadIdx.x;
    if (idx >= G_TOTAL) return;
    int g, kk, n, NP, boff, rem = idx;
    if (rem < 73728)       { g = 0; kk = rem / 384; n = rem % 384; NP = 24; boff = 0; }
    else if (rem < 204800) { rem -= 73728;  g = 1; kk = rem / 512; n = rem % 512; NP = 32; boff = 73728; }
    else                   { rem -= 204800; g = 2; kk = rem / 256; n = rem % 256; NP = 16; boff = 204800; }

    int c = kk & 63, d = n & 127, ib = kk >> 6, ob = n >> 7;
    int w; float s = 1.0f;
    if (g == 0) {
        w = ib * 3 + ob;
    } else if (g == 1) {
        int i = ib & 1, o = ob & 1;
        bool ip = ib < 2, op = ob < 2;
        int base = 9 + i * 4 + o * 2;
        if (ip && op)        w = base;                   // +Wr
        else if (!ip && op)  { w = base + 1; s = -1.f; } // -Wi
        else if (ip && !op)  w = base + 1;               // +Wi
        else                 w = base;                   // +Wr
    } else {
        bool ip = (ib == 0), op = (ob == 0);
        if (ip && op)        w = 17;
        else if (!ip && op)  { w = 18; s = -1.f; }
        else if (ip && !op)  w = 18;
        else                 w = 17;
    }
    int widx = (w * 64 + c) * 128 + d;

    int kt = kk >> 4, k16 = kk & 15, n8 = n >> 3;
    int lane = (n & 7) * 4 + ((k16 & 7) >> 1);
    int slot = (k16 & 1) + ((k16 >> 3) << 1);
    int off  = boff + ((kt * NP + (n8 >> 1)) * 32 + lane) * 8 + ((n8 & 1) << 2) + slot;

    g_B[mat][off] = __float2half(s * W[widx]);
}

// ---------------------------------------------------------------------------
#define MMA(c, a, b0, b1) asm volatile( \
    "mma.sync.aligned.m16n8k16.row.col.f32.f16.f16.f32 " \
    "{%0,%1,%2,%3},{%4,%5,%6,%7},{%8,%9},{%0,%1,%2,%3};\n" \
    : "+f"((c)[0]), "+f"((c)[1]), "+f"((c)[2]), "+f"((c)[3]) \
    : "r"((a).x), "r"((a).y), "r"((a).z), "r"((a).w), "r"(b0), "r"(b1))

__global__ __launch_bounds__(512, 1)
void so2_attn_main(const float* __restrict__ xq, const float* __restrict__ xk, int E) {
    extern __shared__ __half sA[];   // [0]=q frags (32768 halfs), [32768]=k frags
    const int tid = threadIdx.x, lane = tid & 31, warp = tid >> 5;
    const int warpM = warp & 3, warpN = warp >> 2;   // 4 x 4 warp grid
    const int tileE = blockIdx.x * 128;

    float pre[2][2][2];   // [mtl][rowhalf][par] ; head = warpN + par*4
    #pragma unroll
    for (int a = 0; a < 2; a++)
        #pragma unroll
        for (int b = 0; b < 2; b++)
            #pragma unroll
            for (int c = 0; c < 2; c++) pre[a][b][c] = 0.f;

    for (int g = 0; g < 3; ++g) {
        const int Kt = c_KT[g], NP = c_NP[g], NPJ = c_NPJ[g], D = c_D[g];
        __syncthreads();
        // ---- convert x slice -> fragment-major fp16 smem (128 edges) ----
        const int nq = 128 * (D >> 2);
        #pragma unroll
        for (int t = 0; t < 2; ++t) {
            const float* x = t ? xk : xq;
            __half* A = sA + t * 32768;
            for (int q0 = tid; q0 < nq; q0 += 512) {
                int el = q0 / (D >> 2), c = (q0 % (D >> 2)) * 4;
                int ord = c_ord[c_IB0[g] + (c >> 6)];
                int e = tileE + el;
                float4 v = make_float4(0.f, 0.f, 0.f, 0.f);
                if (e < E) v = *(const float4*)(x + ((size_t)e * 9 + ord) * 64 + (c & 63));
                int r = el & 15, mtile = el >> 4;
                int kt = c >> 4, kk0 = c & 15;
                int ln0 = (r & 7) * 4 + ((kk0 & 7) >> 1);
                int hx  = (((kk0 >> 3) << 1) + (r >> 3)) * 2;
                int off = ((mtile * Kt + kt) * 32 + ln0) * 8 + hx;
                *(__half2*)(A + off)     = __floats2half2_rn(v.x, v.y);
                *(__half2*)(A + off + 8) = __floats2half2_rn(v.z, v.w);
            }
        }
        __syncthreads();

        // ---- fused fp16 GEMMs + per-head q*k reduction ----
        const uint4* Bq = (const uint4*)g_B[0] + c_B4[g];
        const uint4* Bk = (const uint4*)g_B[1] + c_B4[g];
        const uint4* Aq = (const uint4*)sA;
        const uint4* Ak = Aq + 4096;
        const int bstep = NP * 32;

        for (int j = 0; j < NPJ; ++j) {
            const int p0 = warpN + (j << 2);
            float cq[2][2][4], ck[2][2][4];   // [mtl][d2][4]
            #pragma unroll
            for (int a = 0; a < 2; a++)
                #pragma unroll
                for (int d2 = 0; d2 < 2; d2++)
                    #pragma unroll
                    for (int i = 0; i < 4; i++) { cq[a][d2][i] = 0.f; ck[a][d2][i] = 0.f; }

            int bi = p0 * 32 + lane;
            uint4 bq = Bq[bi], bk = Bk[bi];

            #pragma unroll 1
            for (int kt = 0; kt < Kt; ++kt) {
                uint4 aq[2], ak[2];
                #pragma unroll
                for (int mtl = 0; mtl < 2; ++mtl) {
                    int ai = (((warpM << 1) + mtl) * Kt + kt) * 32 + lane;
                    aq[mtl] = Aq[ai]; ak[mtl] = Ak[ai];
                }
                int nbi = (kt + 1 < Kt) ? bi + bstep : bi;
                uint4 nbq = Bq[nbi], nbk = Bk[nbi];

                #pragma unroll
                for (int mtl = 0; mtl < 2; ++mtl) {
                    MMA(cq[mtl][0], aq[mtl], bq.x, bq.y);
                    MMA(cq[mtl][1], aq[mtl], bq.z, bq.w);
                    MMA(ck[mtl][0], ak[mtl], bk.x, bk.y);
                    MMA(ck[mtl][1], ak[mtl], bk.z, bk.w);
                }
                bq = nbq; bk = nbk; bi = nbi;
            }

            const int par = j & 1;
            #pragma unroll
            for (int mtl = 0; mtl < 2; ++mtl) {
                pre[mtl][0][par] += cq[mtl][0][0] * ck[mtl][0][0] + cq[mtl][0][1] * ck[mtl][0][1]
                                  + cq[mtl][1][0] * ck[mtl][1][0] + cq[mtl][1][1] * ck[mtl][1][1];
                pre[mtl][1][par] += cq[mtl][0][2] * ck[mtl][0][2] + cq[mtl][0][3] * ck[mtl][0][3]
                                  + cq[mtl][1][2] * ck[mtl][1][2] + cq[mtl][1][3] * ck[mtl][1][3];
            }
        }
    }

    // reduce over the 4-lane n-split group and store pre (unique writer per (e,h))
    #pragma unroll
    for (int a = 0; a < 2; a++)
        #pragma unroll
        for (int b = 0; b < 2; b++)
            #pragma unroll
            for (int c = 0; c < 2; c++) {
                float v = pre[a][b][c];
                v += __shfl_xor_sync(0xffffffffu, v, 1);
                v += __shfl_xor_sync(0xffffffffu, v, 2);
                pre[a][b][c] = v;
            }
    if ((lane & 3) == 0) {
        int gID = lane >> 2;
        #pragma unroll
        for (int mtl = 0; mtl < 2; ++mtl)
            #pragma unroll
            for (int rh = 0; rh < 2; ++rh)
                #pragma unroll
                for (int par = 0; par < 2; ++par) {
                    int e = tileE + ((warpM << 1) + mtl) * 16 + gID + rh * 8;
                    int h = warpN + (par << 2);
                    if (e < E) g_pre[e * 8 + h] = 0.25f * pre[mtl][rh][par];
                }
    }
}

// ---------------------------------------------------------------------------
// Segment softmax
// ---------------------------------------------------------------------------
__device__ __forceinline__ unsigned fenc(float f) {
    unsigned b = __float_as_uint(f);
    return (b & 0x80000000u) ? ~b : (b | 0x80000000u);
}
__device__ __forceinline__ float fdec(unsigned u) {
    unsigned b = (u & 0x80000000u) ? (u & 0x7FFFFFFFu) : ~u;
    return __uint_as_float(b);
}

__global__ void k_init_max() {
    int i = blockIdx.x * blockDim.x + threadIdx.x;
    if (i < NODECAP * 8) g_segmax[i] = 0u;
}
__global__ void k_init_sum() {
    int i = blockIdx.x * blockDim.x + threadIdx.x;
    if (i < NODECAP * 8) g_segsum[i] = 0.f;
}
__global__ void k_zero_pre(int n) {
    int i = blockIdx.x * blockDim.x + threadIdx.x;
    if (i < n) g_pre[i] = 0.f;
}
__global__ void k_max(int E, const int* __restrict__ index) {
    int i = blockIdx.x * blockDim.x + threadIdx.x;
    if (i >= E * 8) return;
    int e = i >> 3, h = i & 7;
    atomicMax(&g_segmax[index[e] * 8 + h], fenc(g_pre[i]));
}
__global__ void k_exp(int E, const int* __restrict__ index, float* __restrict__ out) {
    int i = blockIdx.x * blockDim.x + threadIdx.x;
    if (i >= E * 8) return;
    int e = i >> 3, h = i & 7;
    int seg = index[e] * 8 + h;
    float ex = expf(g_pre[i] - fdec(g_segmax[seg]));
    out[i] = ex;
    atomicAdd(&g_segsum[seg], ex);
}
__global__ void k_norm(int E, const int* __restrict__ index, float* __restrict__ out) {
    int i = blockIdx.x * blockDim.x + threadIdx.x;
    if (i >= E * 8) return;
    int e = i >> 3, h = i & 7;
    out[i] = out[i] / (g_segsum[index[e] * 8 + h] + 1e-16f);
}

// ---------------------------------------------------------------------------
extern "C" void kernel_launch(void* const* d_in, const int* in_sizes, int n_in,
                              void* d_out, int out_size) {
    const float* xq    = (const float*)d_in[0];
    const float* xk    = (const float*)d_in[1];
    const float* Wq    = (const float*)d_in[2];
    const float* Wk    = (const float*)d_in[3];
    const int*   index = (const int*)d_in[4];
    float* out = (float*)d_out;
    int E = in_sizes[0] / (9 * 64);

    cudaFuncSetAttribute(so2_attn_main, cudaFuncAttributeMaxDynamicSharedMemorySize, SMEM_BYTES);

    // launches 0..4 (setup) so the main GEMM is launch #5 for ncu -s 5 -c 1
    k_init_max<<<(NODECAP * 8 + 255) / 256, 256>>>();
    k_init_sum<<<(NODECAP * 8 + 255) / 256, 256>>>();
    prep_w<<<(G_TOTAL + 255) / 256, 256>>>(Wq, 0);
    prep_w<<<(G_TOTAL + 255) / 256, 256>>>(Wk, 1);
    k_zero_pre<<<(E * 8 + 255) / 256, 256>>>(E * 8);

    so2_attn_main<<<(E + 127) / 128, 512, SMEM_BYTES>>>(xq, xk, E);

    int nb = (E * 8 + 255) / 256;
    k_max <<<nb, 256>>>(E, index);
    k_exp <<<nb, 256>>>(E, index, out);
    k_norm<<<nb, 256>>>(E, index, out);
}

// round 8
// speedup vs baseline: 1.9634x; 1.3807x over previous
#include <cuda_runtime.h>
#include <cuda_fp16.h>
#include <math.h>

#define NODECAP 16384
#define G_TOTAL 237568   // 192*384 + 256*512 + 128*256
#define PRECAP  (1<<20)
#define SMEM_BYTES 65536    // 2 mats * 64 edges * 256 cols * 2B

// Prepped fragment-major fp16 weights: [0]=q [1]=k
__device__ __align__(16) __half g_B[2][G_TOTAL];
__device__ float    g_pre[PRECAP];
__device__ unsigned g_segmax[NODECAP * 8];
__device__ float    g_segsum[NODECAP * 8];

__constant__ int c_ord[9] = {0, 2, 6, 3, 7, 1, 5, 8, 4};
__constant__ int c_KT[3]  = {12, 16, 8};
__constant__ int c_NP[3]  = {24, 32, 16};
__constant__ int c_NPJ[3] = {3, 4, 2};          // NP / 8
__constant__ int c_D[3]   = {192, 256, 128};
__constant__ int c_IB0[3] = {0, 3, 7};
__constant__ int c_B4[3]  = {0, 9216, 25600};   // uint4 base per group

// ---------------------------------------------------------------------------
// Weight prep: dense W_eff per |m| group (sign pattern folded), fp16,
// exact mma.m16n8k16 B-fragment order, n8 pairs packed 8 halfs/lane.
// ---------------------------------------------------------------------------
__global__ void prep_w(const float* __restrict__ W, int mat) {
    int idx = blockIdx.x * blockDim.x + threadIdx.x;
    if (idx >= G_TOTAL) return;
    int g, kk, n, NP, boff, rem = idx;
    if (rem < 73728)       { g = 0; kk = rem / 384; n = rem % 384; NP = 24; boff = 0; }
    else if (rem < 204800) { rem -= 73728;  g = 1; kk = rem / 512; n = rem % 512; NP = 32; boff = 73728; }
    else                   { rem -= 204800; g = 2; kk = rem / 256; n = rem % 256; NP = 16; boff = 204800; }

    int c = kk & 63, d = n & 127, ib = kk >> 6, ob = n >> 7;
    int w; float s = 1.0f;
    if (g == 0) {
        w = ib * 3 + ob;
    } else if (g == 1) {
        int i = ib & 1, o = ob & 1;
        bool ip = ib < 2, op = ob < 2;
        int base = 9 + i * 4 + o * 2;
        if (ip && op)        w = base;                   // +Wr
        else if (!ip && op)  { w = base + 1; s = -1.f; } // -Wi
        else if (ip && !op)  w = base + 1;               // +Wi
        else                 w = base;                   // +Wr
    } else {
        bool ip = (ib == 0), op = (ob == 0);
        if (ip && op)        w = 17;
        else if (!ip && op)  { w = 18; s = -1.f; }
        else if (ip && !op)  w = 18;
        else                 w = 17;
    }
    int widx = (w * 64 + c) * 128 + d;

    int kt = kk >> 4, k16 = kk & 15, n8 = n >> 3;
    int lane = (n & 7) * 4 + ((k16 & 7) >> 1);
    int slot = (k16 & 1) + ((k16 >> 3) << 1);
    int off  = boff + ((kt * NP + (n8 >> 1)) * 32 + lane) * 8 + ((n8 & 1) << 2) + slot;

    g_B[mat][off] = __float2half(s * W[widx]);
}

// ---------------------------------------------------------------------------
#define MMA(c, a, b0, b1) asm volatile( \
    "mma.sync.aligned.m16n8k16.row.col.f32.f16.f16.f32 " \
    "{%0,%1,%2,%3},{%4,%5,%6,%7},{%8,%9},{%0,%1,%2,%3};\n" \
    : "+f"((c)[0]), "+f"((c)[1]), "+f"((c)[2]), "+f"((c)[3]) \
    : "r"((a).x), "r"((a).y), "r"((a).z), "r"((a).w), "r"(b0), "r"(b1))

__global__ __launch_bounds__(256, 2)
void so2_attn_main(const float* __restrict__ xq, const float* __restrict__ xk, int E) {
    extern __shared__ __half sA[];   // [0]=q frags (16384 halfs), [16384]=k frags
    const int tid = threadIdx.x, lane = tid & 31, warp = tid >> 5;
    const int warpM = warp & 1, warpN = warp >> 1;
    const int tileE = blockIdx.x * 64;

    float pre[2][2][2];   // [mt][rowhalf][np] ; head = warpN + np*4
    #pragma unroll
    for (int a = 0; a < 2; a++)
        #pragma unroll
        for (int b = 0; b < 2; b++)
            #pragma unroll
            for (int c = 0; c < 2; c++) pre[a][b][c] = 0.f;

    for (int g = 0; g < 3; ++g) {
        const int Kt = c_KT[g], NP = c_NP[g], NPJ = c_NPJ[g], D = c_D[g];
        __syncthreads();
        // ---- convert x slice -> fragment-major fp16 smem (64 edges) ----
        const int nq = 64 * (D >> 2);
        #pragma unroll
        for (int t = 0; t < 2; ++t) {
            const float* x = t ? xk : xq;
            __half* A = sA + t * 16384;
            for (int q0 = tid; q0 < nq; q0 += 256) {
                int el = q0 / (D >> 2), c = (q0 % (D >> 2)) * 4;
                int ord = c_ord[c_IB0[g] + (c >> 6)];
                int e = tileE + el;
                float4 v = make_float4(0.f, 0.f, 0.f, 0.f);
                if (e < E) v = *(const float4*)(x + ((size_t)e * 9 + ord) * 64 + (c & 63));
                int r = el & 15, mtile = el >> 4;
                int kt = c >> 4, kk0 = c & 15;
                int ln0 = (r & 7) * 4 + ((kk0 & 7) >> 1);
                int hx  = (((kk0 >> 3) << 1) + (r >> 3)) * 2;
                int off = ((mtile * Kt + kt) * 32 + ln0) * 8 + hx;
                *(__half2*)(A + off)     = __floats2half2_rn(v.x, v.y);
                *(__half2*)(A + off + 8) = __floats2half2_rn(v.z, v.w);
            }
        }
        __syncthreads();

        // ---- fused fp16 GEMMs + per-head q*k reduction ----
        const uint4* Bq = (const uint4*)g_B[0] + c_B4[g];
        const uint4* Bk = (const uint4*)g_B[1] + c_B4[g];
        const uint4* Aq = (const uint4*)sA;
        const uint4* Ak = Aq + 2048;

        for (int j = 0; j < NPJ; ++j) {
            const int p0 = warpN + j * 8;
            float cq[2][2][2][4], ck[2][2][2][4];   // [np][mt][d2][4]
            #pragma unroll
            for (int a = 0; a < 2; a++)
                #pragma unroll
                for (int b = 0; b < 2; b++)
                    #pragma unroll
                    for (int d2 = 0; d2 < 2; d2++)
                        #pragma unroll
                        for (int i = 0; i < 4; i++) { cq[a][b][d2][i] = 0.f; ck[a][b][d2][i] = 0.f; }

            #pragma unroll 1
            for (int kt = 0; kt < Kt; ++kt) {
                uint4 aq[2], ak[2];
                #pragma unroll
                for (int mt = 0; mt < 2; ++mt) {
                    int ai = ((2 * warpM + mt) * Kt + kt) * 32 + lane;
                    aq[mt] = Aq[ai]; ak[mt] = Ak[ai];
                }
                uint4 bq[2], bk[2];
                #pragma unroll
                for (int np = 0; np < 2; ++np) {
                    int bi = (kt * NP + p0 + np * 4) * 32 + lane;
                    bq[np] = __ldg(Bq + bi); bk[np] = __ldg(Bk + bi);
                }
                #pragma unroll
                for (int np = 0; np < 2; ++np)
                    #pragma unroll
                    for (int mt = 0; mt < 2; ++mt) {
                        MMA(cq[np][mt][0], aq[mt], bq[np].x, bq[np].y);
                        MMA(cq[np][mt][1], aq[mt], bq[np].z, bq[np].w);
                        MMA(ck[np][mt][0], ak[mt], bk[np].x, bk[np].y);
                        MMA(ck[np][mt][1], ak[mt], bk[np].z, bk[np].w);
                    }
            }
            #pragma unroll
            for (int np = 0; np < 2; ++np)
                #pragma unroll
                for (int mt = 0; mt < 2; ++mt) {
                    pre[mt][0][np] += cq[np][mt][0][0] * ck[np][mt][0][0] + cq[np][mt][0][1] * ck[np][mt][0][1]
                                    + cq[np][mt][1][0] * ck[np][mt][1][0] + cq[np][mt][1][1] * ck[np][mt][1][1];
                    pre[mt][1][np] += cq[np][mt][0][2] * ck[np][mt][0][2] + cq[np][mt][0][3] * ck[np][mt][0][3]
                                    + cq[np][mt][1][2] * ck[np][mt][1][2] + cq[np][mt][1][3] * ck[np][mt][1][3];
                }
        }
    }

    // reduce over the 4-lane n-split group and store pre (unique writer per (e,h))
    #pragma unroll
    for (int a = 0; a < 2; a++)
        #pragma unroll
        for (int b = 0; b < 2; b++)
            #pragma unroll
            for (int c = 0; c < 2; c++) {
                float v = pre[a][b][c];
                v += __shfl_xor_sync(0xffffffffu, v, 1);
                v += __shfl_xor_sync(0xffffffffu, v, 2);
                pre[a][b][c] = v;
            }
    if ((lane & 3) == 0) {
        int gID = lane >> 2;
        #pragma unroll
        for (int mt = 0; mt < 2; ++mt)
            #pragma unroll
            for (int rh = 0; rh < 2; ++rh)
                #pragma unroll
                for (int np = 0; np < 2; ++np) {
                    int e = tileE + (2 * warpM + mt) * 16 + gID + rh * 8;
                    int h = warpN + np * 4;
                    if (e < E) g_pre[e * 8 + h] = 0.25f * pre[mt][rh][np];
                }
    }
}

// ---------------------------------------------------------------------------
// Segment softmax
// ---------------------------------------------------------------------------
__device__ __forceinline__ unsigned fenc(float f) {
    unsigned b = __float_as_uint(f);
    return (b & 0x80000000u) ? ~b : (b | 0x80000000u);
}
__device__ __forceinline__ float fdec(unsigned u) {
    unsigned b = (u & 0x80000000u) ? (u & 0x7FFFFFFFu) : ~u;
    return __uint_as_float(b);
}

__global__ void k_init() {
    int i = blockIdx.x * blockDim.x + threadIdx.x;
    if (i < NODECAP * 8) { g_segmax[i] = 0u; g_segsum[i] = 0.f; }
}
__global__ void k_max(int E, const int* __restrict__ index) {
    int i = blockIdx.x * blockDim.x + threadIdx.x;
    if (i >= E * 8) return;
    int e = i >> 3, h = i & 7;
    atomicMax(&g_segmax[index[e] * 8 + h], fenc(g_pre[i]));
}
__global__ void k_exp(int E, const int* __restrict__ index, float* __restrict__ out) {
    int i = blockIdx.x * blockDim.x + threadIdx.x;
    if (i >= E * 8) return;
    int e = i >> 3, h = i & 7;
    int seg = index[e] * 8 + h;
    float ex = expf(g_pre[i] - fdec(g_segmax[seg]));
    out[i] = ex;
    atomicAdd(&g_segsum[seg], ex);
}
__global__ void k_norm(int E, const int* __restrict__ index, float* __restrict__ out) {
    int i = blockIdx.x * blockDim.x + threadIdx.x;
    if (i >= E * 8) return;
    int e = i >> 3, h = i & 7;
    out[i] = out[i] / (g_segsum[index[e] * 8 + h] + 1e-16f);
}

// ---------------------------------------------------------------------------
extern "C" void kernel_launch(void* const* d_in, const int* in_sizes, int n_in,
                              void* d_out, int out_size) {
    const float* xq    = (const float*)d_in[0];
    const float* xk    = (const float*)d_in[1];
    const float* Wq    = (const float*)d_in[2];
    const float* Wk    = (const float*)d_in[3];
    const int*   index = (const int*)d_in[4];
    float* out = (float*)d_out;
    int E = in_sizes[0] / (9 * 64);

    cudaFuncSetAttribute(so2_attn_main, cudaFuncAttributeMaxDynamicSharedMemorySize, SMEM_BYTES);

    // our launch idx 3 == global idx 5 (2 hidden harness launches) for ncu -s 5 -c 1
    prep_w<<<(G_TOTAL + 255) / 256, 256>>>(Wq, 0);
    prep_w<<<(G_TOTAL + 255) / 256, 256>>>(Wk, 1);
    k_init<<<(NODECAP * 8 + 255) / 256, 256>>>();

    so2_attn_main<<<(E + 63) / 64, 256, SMEM_BYTES>>>(xq, xk, E);

    int nb = (E * 8 + 255) / 256;
    k_max <<<nb, 256>>>(E, index);
    k_exp <<<nb, 256>>>(E, index, out);
    k_norm<<<nb, 256>>>(E, index, out);
}

// round 9
// speedup vs baseline: 2.0954x; 1.0672x over previous
#include <cuda_runtime.h>
#include <cuda_fp16.h>
#include <math.h>
#include <stdint.h>

#define NODECAP 16384
#define G_TOTAL 237568   // 192*384 + 256*512 + 128*256
#define PRECAP  (1<<20)
#define SMEM_BYTES 90112    // 64KB A frags + 24KB B ring (3 x 8KB)

// Prepped fragment-major fp16 weights: [0]=q [1]=k
__device__ __align__(16) __half g_B[2][G_TOTAL];
__device__ float    g_pre[PRECAP];
__device__ unsigned g_segmax[NODECAP * 8];
__device__ float    g_segsum[NODECAP * 8];

__constant__ int c_ord[9] = {0, 2, 6, 3, 7, 1, 5, 8, 4};
__constant__ int c_KT[3]  = {12, 16, 8};
__constant__ int c_NP[3]  = {24, 32, 16};
__constant__ int c_NPJ[3] = {3, 4, 2};          // NP / 8
__constant__ int c_D[3]   = {192, 256, 128};
__constant__ int c_IB0[3] = {0, 3, 7};
__constant__ int c_B4[3]  = {0, 9216, 25600};   // uint4 base per group

// ---------------------------------------------------------------------------
// Weight prep: dense W_eff per |m| group (sign pattern folded), fp16,
// exact mma.m16n8k16 B-fragment order, n8 pairs packed 8 halfs/lane.
// (j,kt) blocks of 8 n8-pairs land CONTIGUOUS (4KB per mat) for cp.async.
// ---------------------------------------------------------------------------
__global__ void prep_w(const float* __restrict__ W, int mat) {
    int idx = blockIdx.x * blockDim.x + threadIdx.x;
    if (idx >= G_TOTAL) return;
    int g, kk, n, NP, boff, rem = idx;
    if (rem < 73728)       { g = 0; kk = rem / 384; n = rem % 384; NP = 24; boff = 0; }
    else if (rem < 204800) { rem -= 73728;  g = 1; kk = rem / 512; n = rem % 512; NP = 32; boff = 73728; }
    else                   { rem -= 204800; g = 2; kk = rem / 256; n = rem % 256; NP = 16; boff = 204800; }

    int c = kk & 63, d = n & 127, ib = kk >> 6, ob = n >> 7;
    int w; float s = 1.0f;
    if (g == 0) {
        w = ib * 3 + ob;
    } else if (g == 1) {
        int i = ib & 1, o = ob & 1;
        bool ip = ib < 2, op = ob < 2;
        int base = 9 + i * 4 + o * 2;
        if (ip && op)        w = base;                   // +Wr
        else if (!ip && op)  { w = base + 1; s = -1.f; } // -Wi
        else if (ip && !op)  w = base + 1;               // +Wi
        else                 w = base;                   // +Wr
    } else {
        bool ip = (ib == 0), op = (ob == 0);
        if (ip && op)        w = 17;
        else if (!ip && op)  { w = 18; s = -1.f; }
        else if (ip && !op)  w = 18;
        else                 w = 17;
    }
    int widx = (w * 64 + c) * 128 + d;

    int kt = kk >> 4, k16 = kk & 15, n8 = n >> 3;
    int lane = (n & 7) * 4 + ((k16 & 7) >> 1);
    int slot = (k16 & 1) + ((k16 >> 3) << 1);
    int off  = boff + ((kt * NP + (n8 >> 1)) * 32 + lane) * 8 + ((n8 & 1) << 2) + slot;

    g_B[mat][off] = __float2half(s * W[widx]);
}

// ---------------------------------------------------------------------------
__device__ __forceinline__ uint32_t s2u(const void* p) {
    uint32_t a;
    asm("{ .reg .u64 t; cvta.to.shared.u64 t, %1; cvt.u32.u64 %0, t; }" : "=r"(a) : "l"(p));
    return a;
}
#define CPA16(d, sp)  asm volatile("cp.async.cg.shared.global [%0], [%1], 16;" :: "r"(d), "l"(sp) : "memory")
#define CPA_COMMIT()  asm volatile("cp.async.commit_group;" ::: "memory")
#define CPA_WAIT0()   asm volatile("cp.async.wait_group 0;" ::: "memory")
#define CPA_WAIT1()   asm volatile("cp.async.wait_group 1;" ::: "memory")

#define MMA(c, a, b0, b1) asm volatile( \
    "mma.sync.aligned.m16n8k16.row.col.f32.f16.f16.f32 " \
    "{%0,%1,%2,%3},{%4,%5,%6,%7},{%8,%9},{%0,%1,%2,%3};\n" \
    : "+f"((c)[0]), "+f"((c)[1]), "+f"((c)[2]), "+f"((c)[3]) \
    : "r"((a).x), "r"((a).y), "r"((a).z), "r"((a).w), "r"(b0), "r"(b1))

__global__ __launch_bounds__(256, 2)
void so2_attn_main(const float* __restrict__ xq, const float* __restrict__ xk, int E) {
    extern __shared__ __half sA[];   // [0]=q frags (16384 halfs), [16384]=k frags
    uint4* sB = (uint4*)(sA + 32768);        // ring: 3 stages x 512 uint4 (8KB)
    const uint32_t sB_u32 = s2u(sB);
    const int tid = threadIdx.x, lane = tid & 31, warp = tid >> 5;
    const int warpM = warp & 1, warpN = warp >> 1;
    const int tileE = blockIdx.x * 64;

    float pre[2][2][2];   // [mt][rowhalf][np] ; head = warpN + np*4
    #pragma unroll
    for (int a = 0; a < 2; a++)
        #pragma unroll
        for (int b = 0; b < 2; b++)
            #pragma unroll
            for (int c = 0; c < 2; c++) pre[a][b][c] = 0.f;

    for (int g = 0; g < 3; ++g) {
        const int Kt = c_KT[g], NP = c_NP[g], NPJ = c_NPJ[g], D = c_D[g];
        __syncthreads();   // previous group's compute fully done before rewriting sA
        // ---- convert x slice -> fragment-major fp16 smem (64 edges) ----
        const int nq = 64 * (D >> 2);
        #pragma unroll
        for (int t = 0; t < 2; ++t) {
            const float* x = t ? xk : xq;
            __half* A = sA + t * 16384;
            for (int q0 = tid; q0 < nq; q0 += 256) {
                int el = q0 / (D >> 2), c = (q0 % (D >> 2)) * 4;
                int ord = c_ord[c_IB0[g] + (c >> 6)];
                int e = tileE + el;
                float4 v = make_float4(0.f, 0.f, 0.f, 0.f);
                if (e < E) v = *(const float4*)(x + ((size_t)e * 9 + ord) * 64 + (c & 63));
                int r = el & 15, mtile = el >> 4;
                int kt = c >> 4, kk0 = c & 15;
                int ln0 = (r & 7) * 4 + ((kk0 & 7) >> 1);
                int hx  = (((kk0 >> 3) << 1) + (r >> 3)) * 2;
                int off = ((mtile * Kt + kt) * 32 + ln0) * 8 + hx;
                *(__half2*)(A + off)     = __floats2half2_rn(v.x, v.y);
                *(__half2*)(A + off + 8) = __floats2half2_rn(v.z, v.w);
            }
        }
        __syncthreads();

        // ---- fused fp16 GEMMs + per-head q*k reduction, cp.async B ring ----
        const uint4* Bq = (const uint4*)g_B[0] + c_B4[g];
        const uint4* Bk = (const uint4*)g_B[1] + c_B4[g];
        const uint4* Aq = (const uint4*)sA;
        const uint4* Ak = Aq + 2048;
        const int S = NPJ * Kt;

        // issue(s, stage): stage in {0,1,2}; (j,kt) block is contiguous 256 uint4 per mat
        #define ISSUE(ss, stg) do { \
            int _j = (ss) / Kt, _kt = (ss) - _j * Kt; \
            int _blk = (_kt * NP + _j * 8) * 32; \
            uint32_t _d = sB_u32 + (((stg) * 512 + tid) << 4); \
            CPA16(_d, Bq + _blk + tid); \
            CPA16(_d + 4096, Bk + _blk + tid); \
            CPA_COMMIT(); \
        } while (0)

        ISSUE(0, 0);
        ISSUE(1, 1);

        int s = 0;
        for (int j = 0; j < NPJ; ++j) {
            float cq[2][2][2][4], ck[2][2][2][4];   // [np][mt][d2][4]
            #pragma unroll
            for (int a = 0; a < 2; a++)
                #pragma unroll
                for (int b = 0; b < 2; b++)
                    #pragma unroll
                    for (int d2 = 0; d2 < 2; d2++)
                        #pragma unroll
                        for (int i = 0; i < 4; i++) { cq[a][b][d2][i] = 0.f; ck[a][b][d2][i] = 0.f; }

            #pragma unroll 1
            for (int kt = 0; kt < Kt; ++kt, ++s) {
                if (s + 1 < S) CPA_WAIT1(); else CPA_WAIT0();
                __syncthreads();                      // stage s visible; stage (s+2)%3 free
                if (s + 2 < S) ISSUE(s + 2, (s + 2) % 3);

                const uint4* bb = sB + (s % 3) * 512;
                uint4 aq[2], ak[2];
                #pragma unroll
                for (int mt = 0; mt < 2; ++mt) {
                    int ai = ((2 * warpM + mt) * Kt + kt) * 32 + lane;
                    aq[mt] = Aq[ai]; ak[mt] = Ak[ai];
                }
                uint4 bq[2], bk[2];
                #pragma unroll
                for (int np = 0; np < 2; ++np) {
                    int lp = (warpN + np * 4) * 32 + lane;
                    bq[np] = bb[lp]; bk[np] = bb[256 + lp];
                }
                #pragma unroll
                for (int np = 0; np < 2; ++np)
                    #pragma unroll
                    for (int mt = 0; mt < 2; ++mt) {
                        MMA(cq[np][mt][0], aq[mt], bq[np].x, bq[np].y);
                        MMA(cq[np][mt][1], aq[mt], bq[np].z, bq[np].w);
                        MMA(ck[np][mt][0], ak[mt], bk[np].x, bk[np].y);
                        MMA(ck[np][mt][1], ak[mt], bk[np].z, bk[np].w);
                    }
            }
            #pragma unroll
            for (int np = 0; np < 2; ++np)
                #pragma unroll
                for (int mt = 0; mt < 2; ++mt) {
                    pre[mt][0][np] += cq[np][mt][0][0] * ck[np][mt][0][0] + cq[np][mt][0][1] * ck[np][mt][0][1]
                                    + cq[np][mt][1][0] * ck[np][mt][1][0] + cq[np][mt][1][1] * ck[np][mt][1][1];
                    pre[mt][1][np] += cq[np][mt][0][2] * ck[np][mt][0][2] + cq[np][mt][0][3] * ck[np][mt][0][3]
                                    + cq[np][mt][1][2] * ck[np][mt][1][2] + cq[np][mt][1][3] * ck[np][mt][1][3];
                }
        }
        #undef ISSUE
    }

    // reduce over the 4-lane n-split group and store pre (unique writer per (e,h))
    #pragma unroll
    for (int a = 0; a < 2; a++)
        #pragma unroll
        for (int b = 0; b < 2; b++)
            #pragma unroll
            for (int c = 0; c < 2; c++) {
                float v = pre[a][b][c];
                v += __shfl_xor_sync(0xffffffffu, v, 1);
                v += __shfl_xor_sync(0xffffffffu, v, 2);
                pre[a][b][c] = v;
            }
    if ((lane & 3) == 0) {
        int gID = lane >> 2;
        #pragma unroll
        for (int mt = 0; mt < 2; ++mt)
            #pragma unroll
            for (int rh = 0; rh < 2; ++rh)
                #pragma unroll
                for (int np = 0; np < 2; ++np) {
                    int e = tileE + (2 * warpM + mt) * 16 + gID + rh * 8;
                    int h = warpN + np * 4;
                    if (e < E) g_pre[e * 8 + h] = 0.25f * pre[mt][rh][np];
                }
    }
}

// ---------------------------------------------------------------------------
// Segment softmax
// ---------------------------------------------------------------------------
__device__ __forceinline__ unsigned fenc(float f) {
    unsigned b = __float_as_uint(f);
    return (b & 0x80000000u) ? ~b : (b | 0x80000000u);
}
__device__ __forceinline__ float fdec(unsigned u) {
    unsigned b = (u & 0x80000000u) ? (u & 0x7FFFFFFFu) : ~u;
    return __uint_as_float(b);
}

__global__ void k_init() {
    int i = blockIdx.x * blockDim.x + threadIdx.x;
    if (i < NODECAP * 8) { g_segmax[i] = 0u; g_segsum[i] = 0.f; }
}
__global__ void k_max(int E, const int* __restrict__ index) {
    int i = blockIdx.x * blockDim.x + threadIdx.x;
    if (i >= E * 8) return;
    int e = i >> 3, h = i & 7;
    atomicMax(&g_segmax[index[e] * 8 + h], fenc(g_pre[i]));
}
__global__ void k_exp(int E, const int* __restrict__ index, float* __restrict__ out) {
    int i = blockIdx.x * blockDim.x + threadIdx.x;
    if (i >= E * 8) return;
    int e = i >> 3, h = i & 7;
    int seg = index[e] * 8 + h;
    float ex = expf(g_pre[i] - fdec(g_segmax[seg]));
    out[i] = ex;
    atomicAdd(&g_segsum[seg], ex);
}
__global__ void k_norm(int E, const int* __restrict__ index, float* __restrict__ out) {
    int i = blockIdx.x * blockDim.x + threadIdx.x;
    if (i >= E * 8) return;
    int e = i >> 3, h = i & 7;
    out[i] = out[i] / (g_segsum[index[e] * 8 + h] + 1e-16f);
}

// ---------------------------------------------------------------------------
extern "C" void kernel_launch(void* const* d_in, const int* in_sizes, int n_in,
                              void* d_out, int out_size) {
    const float* xq    = (const float*)d_in[0];
    const float* xk    = (const float*)d_in[1];
    const float* Wq    = (const float*)d_in[2];
    const float* Wk    = (const float*)d_in[3];
    const int*   index = (const int*)d_in[4];
    float* out = (float*)d_out;
    int E = in_sizes[0] / (9 * 64);

    cudaFuncSetAttribute(so2_attn_main, cudaFuncAttributeMaxDynamicSharedMemorySize, SMEM_BYTES);

    // our launch idx 3 == global idx 5 (2 hidden harness launches) for ncu -s 5 -c 1
    prep_w<<<(G_TOTAL + 255) / 256, 256>>>(Wq, 0);
    prep_w<<<(G_TOTAL + 255) / 256, 256>>>(Wk, 1);
    k_init<<<(NODECAP * 8 + 255) / 256, 256>>>();

    so2_attn_main<<<(E + 63) / 64, 256, SMEM_BYTES>>>(xq, xk, E);

    int nb = (E * 8 + 255) / 256;
    k_max <<<nb, 256>>>(E, index);
    k_exp <<<nb, 256>>>(E, index, out);
    k_norm<<<nb, 256>>>(E, index, out);
}